// round 8
// baseline (speedup 1.0000x reference)
#include <cuda_runtime.h>
#include <cuda_fp16.h>
#include <math.h>
#include <stdint.h>

// ---------------- problem constants ----------------
#define LSEQ 2048
#define DMODEL 768
#define KDIM 768
#define NHEAD 12
#define DHEAD 64
#define NCHUNK 16
#define CSIZE 128
#define LN_EPS 1e-5f
#define DEN_EPS 1e-6f

// ---------------- scratch (device globals) ----------------
__device__ __align__(128) __half g_a   [LSEQ * DMODEL];   // LN(x) fp16
__device__ __align__(128) __half g_x   [LSEQ * DMODEL];   // x fp16
__device__ __align__(128) __half g_wqkv[2304 * KDIM];     // W_qkv^T fp16
__device__ __align__(128) __half g_wsc [3072 * KDIM];     // [W_sem;W_ctx]^T fp16
__device__ __align__(128) __half g_wpr [768 * KDIM];      // W_proj^T fp16
__device__ __align__(128) __half g_at  [LSEQ * DMODEL];   // attn out fp16
__device__ __align__(128) float g_bsc[3072];
__device__ __align__(128) float g_qkv[LSEQ * 3 * DMODEL];
__device__ __align__(128) float g_semctx[LSEQ * 3072];
__device__ float g_qf[NHEAD * LSEQ * DHEAD];
__device__ float g_kf[NHEAD * LSEQ * DHEAD];
__device__ float g_vv[NHEAD * LSEQ * DHEAD];
__device__ float g_S [NHEAD * NCHUNK * DHEAD * DHEAD];
__device__ float g_Z [NHEAD * NCHUNK * DHEAD];

// ---------------- PTX helpers (family-portable only) ----------------
__device__ __forceinline__ uint32_t smem_u32(const void* p) {
    uint32_t a;
    asm("{ .reg .u64 t; cvta.to.shared.u64 t, %1; cvt.u32.u64 %0, t; }" : "=r"(a) : "l"(p));
    return a;
}
__device__ __forceinline__ void cp_async16(uint32_t dst, const void* src) {
    asm volatile("cp.async.cg.shared.global [%0], [%1], 16;" :: "r"(dst), "l"(src));
}
__device__ __forceinline__ void cp_commit() {
    asm volatile("cp.async.commit_group;" ::: "memory");
}
__device__ __forceinline__ void cp_wait1() {
    asm volatile("cp.async.wait_group 1;" ::: "memory");
}
#define LDSM4(r0, r1, r2, r3, a) \
    asm volatile("ldmatrix.sync.aligned.m8n8.x4.shared.b16 {%0,%1,%2,%3}, [%4];" \
                 : "=r"(r0), "=r"(r1), "=r"(r2), "=r"(r3) : "r"(a))
#define MMAF16(d, a0, a1, a2, a3, b0, b1) \
    asm volatile("mma.sync.aligned.m16n8k16.row.col.f32.f16.f16.f32 " \
                 "{%0,%1,%2,%3}, {%4,%5,%6,%7}, {%8,%9}, {%0,%1,%2,%3};" \
                 : "+f"((d)[0]), "+f"((d)[1]), "+f"((d)[2]), "+f"((d)[3]) \
                 : "r"(a0), "r"(a1), "r"(a2), "r"(a3), "r"(b0), "r"(b1))

// ---------------- GEMM: C[2048,Ntot] = A @ B^T + bias (fp16, BK=64) ----------------
#define BK 64
#define ROWB 144                      // 128 B data + 16 B pad -> conflict-free ldmatrix
#define TILEB (128 * ROWB)            // 18432 B per 128x64 tile
#define STAGEB (2 * TILEB)            // A, B
#define NSTAGE 3
#define GEMM_SMEM (NSTAGE * STAGEB)   // 110592 B -> 2 CTAs/SM
#define NKT (KDIM / BK)               // 12

__device__ __forceinline__ void g_load_stage(
    uint32_t smem_base, int s, int tid,
    const __half* a, const __half* b)
{
    uint32_t stb = smem_base + (uint32_t)(s % NSTAGE) * STAGEB;
    int kk = s * BK;
    #pragma unroll
    for (int t = 0; t < 2; t++) {
        const __half* base = t ? b : a;
        #pragma unroll
        for (int i = 0; i < 4; i++) {
            int c = tid + i * 256;          // 0..1023
            int r = c >> 3;                 // 0..127
            int seg = c & 7;                // 0..7 (8 x 16B = 128B row)
            cp_async16(stb + (uint32_t)t * TILEB + (uint32_t)(r * ROWB + seg * 16),
                       base + (size_t)r * KDIM + kk + seg * 8);
        }
    }
}

__global__ __launch_bounds__(256, 2)
void gemm_mma(const __half* __restrict__ A, const __half* __restrict__ BT,
              const float* __restrict__ bias, float* __restrict__ C, int Ntot)
{
    extern __shared__ __align__(128) char smem[];
    const int tid = threadIdx.x;
    const int wid = tid >> 5;
    const int lane = tid & 31;
    const int wm = wid & 1;        // M: 2 x 64
    const int wn = wid >> 1;       // N: 4 x 32
    const int bx = blockIdx.x, by = blockIdx.y;

    uint32_t smem_base = smem_u32(smem);

    const __half* a = A + (size_t)by * 128 * KDIM;
    const __half* b = BT + (size_t)bx * 128 * KDIM;

    float acc[4][4][4];
    #pragma unroll
    for (int i = 0; i < 4; i++)
        #pragma unroll
        for (int j = 0; j < 4; j++)
            #pragma unroll
            for (int t = 0; t < 4; t++) acc[i][j][t] = 0.f;

    const uint32_t a_row = (uint32_t)(lane & 15);
    const uint32_t a_byt = (uint32_t)((lane >> 4) * 16);
    const uint32_t b_row = (uint32_t)((lane & 7) + ((lane >> 4) << 3));
    const uint32_t b_byt = (uint32_t)(((lane >> 3) & 1) * 16);

    // prologue: 2 stages in flight
    g_load_stage(smem_base, 0, tid, a, b); cp_commit();
    g_load_stage(smem_base, 1, tid, a, b); cp_commit();

    for (int s = 0; s < NKT; s++) {
        cp_wait1();                 // group s retired
        __syncthreads();
        if (s + 2 < NKT) g_load_stage(smem_base, s + 2, tid, a, b);
        cp_commit();

        uint32_t stb = smem_base + (uint32_t)(s % NSTAGE) * STAGEB;
        #pragma unroll
        for (int k16 = 0; k16 < 4; k16++) {
            const uint32_t koff = (uint32_t)(k16 * 32);
            uint32_t af[4][4];
            #pragma unroll
            for (int mt = 0; mt < 4; mt++) {
                uint32_t addr = stb + (uint32_t)(wm * 64 + mt * 16 + a_row) * ROWB
                              + koff + a_byt;
                LDSM4(af[mt][0], af[mt][1], af[mt][2], af[mt][3], addr);
            }
            uint32_t bf[2][4];
            #pragma unroll
            for (int nb = 0; nb < 2; nb++) {
                uint32_t addr = stb + TILEB + (uint32_t)(wn * 32 + nb * 16 + b_row) * ROWB
                              + koff + b_byt;
                LDSM4(bf[nb][0], bf[nb][1], bf[nb][2], bf[nb][3], addr);
            }
            #pragma unroll
            for (int mt = 0; mt < 4; mt++)
                #pragma unroll
                for (int nt = 0; nt < 4; nt++)
                    MMAF16(acc[mt][nt],
                           af[mt][0], af[mt][1], af[mt][2], af[mt][3],
                           bf[nt >> 1][(nt & 1) * 2], bf[nt >> 1][(nt & 1) * 2 + 1]);
        }
    }

    int r0 = by * 128 + wm * 64 + (lane >> 2);
    int c0 = bx * 128 + wn * 32 + (lane & 3) * 2;
    #pragma unroll
    for (int mt = 0; mt < 4; mt++) {
        #pragma unroll
        for (int nt = 0; nt < 4; nt++) {
            int r = r0 + mt * 16;
            int c = c0 + nt * 8;
            float2 v0 = { acc[mt][nt][0] + bias[c], acc[mt][nt][1] + bias[c + 1] };
            float2 v1 = { acc[mt][nt][2] + bias[c], acc[mt][nt][3] + bias[c + 1] };
            *(float2*)&C[(size_t)r * Ntot + c] = v0;
            *(float2*)&C[(size_t)(r + 8) * Ntot + c] = v1;
        }
    }
}

// ---------------- merged weight transpose + fp16 convert (one launch) ----------------
__global__ void transpose_split_all(const float* __restrict__ Wq,
                                    const float* __restrict__ Ws,
                                    const float* __restrict__ Wc,
                                    const float* __restrict__ Wp)
{
    __shared__ float tile[32][33];
    int bx = blockIdx.x;
    const float* W; int N, rowOff;
    __half* oT;
    if (bx < 72)       { W = Wq; N = 2304; rowOff = 0;    oT = g_wqkv; }
    else if (bx < 120) { W = Ws; N = 1536; rowOff = 0;    oT = g_wsc;  bx -= 72; }
    else if (bx < 168) { W = Wc; N = 1536; rowOff = 1536; oT = g_wsc;  bx -= 120; }
    else               { W = Wp; N = 768;  rowOff = 0;    oT = g_wpr;  bx -= 168; }

    int n0 = bx * 32, k0 = blockIdx.y * 32;
    int tx = threadIdx.x, ty = threadIdx.y;   // (32, 8)
    #pragma unroll
    for (int i = 0; i < 4; i++)
        tile[ty + i * 8][tx] = W[(size_t)(k0 + ty + i * 8) * N + n0 + tx];
    __syncthreads();
    #pragma unroll
    for (int i = 0; i < 4; i++) {
        int n = ty + i * 8;
        oT[(size_t)(rowOff + n0 + n) * KDIM + k0 + tx] = __float2half(tile[tx][n]);
    }
}

__global__ void concat_bias(const float* __restrict__ bs, const float* __restrict__ bc) {
    int i = blockIdx.x * 256 + threadIdx.x;
    if (i < 1536) g_bsc[i] = bs[i];
    else if (i < 3072) g_bsc[i] = bc[i - 1536];
}

// ---------------- LayerNorm + fp16 convert (also converts raw x) ----------------
__global__ void ln_split_kernel(const float* __restrict__ x,
                                const float* __restrict__ gamma,
                                const float* __restrict__ beta) {
    int row = blockIdx.x;
    const float* xr = x + (size_t)row * DMODEL;
    int tid = threadIdx.x;
    __shared__ float red[8];

    float s = 0.f;
    for (int i = tid; i < DMODEL; i += 256) s += xr[i];
    #pragma unroll
    for (int o = 16; o > 0; o >>= 1) s += __shfl_down_sync(0xffffffffu, s, o);
    if ((tid & 31) == 0) red[tid >> 5] = s;
    __syncthreads();
    if (tid < 8) {
        s = red[tid];
        #pragma unroll
        for (int o = 4; o > 0; o >>= 1) s += __shfl_down_sync(0xffu, s, o);
        if (tid == 0) red[0] = s;
    }
    __syncthreads();
    float mu = red[0] * (1.f / DMODEL);
    __syncthreads();

    float v = 0.f;
    for (int i = tid; i < DMODEL; i += 256) { float d = xr[i] - mu; v += d * d; }
    #pragma unroll
    for (int o = 16; o > 0; o >>= 1) v += __shfl_down_sync(0xffffffffu, v, o);
    if ((tid & 31) == 0) red[tid >> 5] = v;
    __syncthreads();
    if (tid < 8) {
        v = red[tid];
        #pragma unroll
        for (int o = 4; o > 0; o >>= 1) v += __shfl_down_sync(0xffu, v, o);
        if (tid == 0) red[0] = v;
    }
    __syncthreads();
    float inv = rsqrtf(red[0] * (1.f / DMODEL) + LN_EPS);

    for (int i = tid; i < DMODEL; i += 256) {
        float xv = xr[i];
        float ln = (xv - mu) * inv * gamma[i] + beta[i];
        g_a[(size_t)row * DMODEL + i] = __float2half(ln);
        g_x[(size_t)row * DMODEL + i] = __float2half(xv);
    }
}

// ---------------- fused gate/features + per-chunk state sums ----------------
__device__ __forceinline__ float softplus_fast(float x) {
    return (x > 0.f) ? x + __logf(1.f + __expf(-x)) : __logf(1.f + __expf(x));
}

#define SMEM_FS (2 * CSIZE * DHEAD * 4)   // 65536 B

__global__ __launch_bounds__(256)
void feat_sums_kernel() {
    int h = blockIdx.x / NCHUNK;
    int c = blockIdx.x % NCHUNK;
    extern __shared__ float sh[];
    float* ks = sh;                    // [128][64]
    float* vs = sh + CSIZE * DHEAD;    // [128][64]
    int tid = threadIdx.x;
    int l0 = c * CSIZE;

    // features: 8192 elems, 32 per thread, coalesced (consecutive tid -> consecutive dh)
    #pragma unroll 4
    for (int i = 0; i < 32; i++) {
        int e = i * 256 + tid;
        int r = e >> 6;
        int dh = e & 63;
        int l = l0 + r;
        int d = h * 64 + dh;
        const float* scr = g_semctx + (size_t)l * 3072;
        float sa = softplus_fast(scr[d]);
        float sp = scr[768 + d];
        float ca = softplus_fast(scr[1536 + d]);
        float cp = scr[2304 + d];
        float z = sa * ca * __cosf(sp - cp);
        float gate = 1.f / (1.f + __expf(-z));

        const float* qr = g_qkv + (size_t)l * 2304;
        float q = qr[d];
        float k = qr[768 + d] * gate;
        float v = qr[1536 + d];
        float qf = (q > 0.f) ? q + 1.f : __expf(q);
        float kf = (k > 0.f) ? k + 1.f : __expf(k);

        ks[r * DHEAD + dh] = kf;
        vs[r * DHEAD + dh] = v;
        size_t o = (size_t)h * LSEQ * DHEAD + (size_t)l * DHEAD + dh;
        g_qf[o] = qf;
        g_kf[o] = kf;
        g_vv[o] = v;
    }
    __syncthreads();

    // S = sum_p k_p (x) v_p ; Z = sum_p k_p
    int te = tid & 15;
    int td = tid >> 4;
    float acc[4][4];
    #pragma unroll
    for (int i = 0; i < 4; i++)
        #pragma unroll
        for (int j = 0; j < 4; j++) acc[i][j] = 0.f;
    float zacc[4] = {0.f, 0.f, 0.f, 0.f};

    #pragma unroll 8
    for (int p = 0; p < CSIZE; p++) {
        float kk[4], vvv[4];
        #pragma unroll
        for (int i = 0; i < 4; i++) kk[i] = ks[p * DHEAD + td * 4 + i];
        #pragma unroll
        for (int j = 0; j < 4; j++) vvv[j] = vs[p * DHEAD + te * 4 + j];
        #pragma unroll
        for (int i = 0; i < 4; i++)
            #pragma unroll
            for (int j = 0; j < 4; j++)
                acc[i][j] = fmaf(kk[i], vvv[j], acc[i][j]);
        if (te == 0) {
            #pragma unroll
            for (int i = 0; i < 4; i++) zacc[i] += kk[i];
        }
    }

    float* Sb = g_S + (size_t)(h * NCHUNK + c) * DHEAD * DHEAD;
    #pragma unroll
    for (int i = 0; i < 4; i++)
        #pragma unroll
        for (int j = 0; j < 4; j++)
            Sb[(size_t)(td * 4 + i) * DHEAD + te * 4 + j] = acc[i][j];
    if (te == 0) {
        float* Zb = g_Z + (size_t)(h * NCHUNK + c) * DHEAD;
        #pragma unroll
        for (int i = 0; i < 4; i++) Zb[td * 4 + i] = zacc[i];
    }
}

// ---------------- phase B: exclusive scan over chunks (grid (12,4)) ----------------
__global__ __launch_bounds__(256)
void scan_states_kernel() {
    int h = blockIdx.x;
    int part = blockIdx.y;
    int tid = threadIdx.x;
    float pref[4] = {0.f, 0.f, 0.f, 0.f};
    float prefz = 0.f;

    for (int c = 0; c < NCHUNK; c++) {
        float* Sb = g_S + (size_t)(h * NCHUNK + c) * DHEAD * DHEAD + part * 1024;
        #pragma unroll
        for (int i = 0; i < 4; i++) {
            int idx = tid + i * 256;
            float cur = Sb[idx];
            Sb[idx] = pref[i];
            pref[i] += cur;
        }
        if (part == 0 && tid < DHEAD) {
            float* Zb = g_Z + (size_t)(h * NCHUNK + c) * DHEAD;
            float cur = Zb[tid];
            Zb[tid] = prefz;
            prefz += cur;
        }
    }
}

// ---------------- phase C: per-chunk causal output (K,V in smem; P,Z via L1) ----------------
#define SMEM_C (2 * CSIZE * DHEAD * 4)   // 65536 B

__global__ __launch_bounds__(128)
void chunk_attn_kernel() {
    int h = blockIdx.x / NCHUNK;
    int c = blockIdx.x % NCHUNK;
    extern __shared__ float sh[];
    float* Ks = sh;
    float* Vs = Ks + CSIZE * DHEAD;

    int tid = threadIdx.x;
    size_t base = (size_t)h * LSEQ * DHEAD + (size_t)c * CSIZE * DHEAD;

    const float4* Kg = (const float4*)(g_kf + base);
    const float4* Vg = (const float4*)(g_vv + base);
    for (int j = tid; j < CSIZE * DHEAD / 4; j += 128) {
        ((float4*)Ks)[j] = Kg[j];
        ((float4*)Vs)[j] = Vg[j];
    }
    __syncthreads();

    float q[DHEAD];
    {
        const float4* qp = (const float4*)(g_qf + base + (size_t)tid * DHEAD);
        #pragma unroll
        for (int i = 0; i < DHEAD / 4; i++) {
            float4 t = qp[i];
            q[4 * i + 0] = t.x; q[4 * i + 1] = t.y; q[4 * i + 2] = t.z; q[4 * i + 3] = t.w;
        }
    }

    const float* Pg = g_S + (size_t)(h * NCHUNK + c) * DHEAD * DHEAD;
    const float* Zg = g_Z + (size_t)(h * NCHUNK + c) * DHEAD;

    float out[DHEAD];
    float den = 0.f;
    #pragma unroll
    for (int d = 0; d < DHEAD; d++) den = fmaf(q[d], __ldg(&Zg[d]), den);
    #pragma unroll
    for (int e = 0; e < DHEAD; e++) out[e] = 0.f;
    #pragma unroll 4
    for (int d = 0; d < DHEAD; d++) {
        float qd = q[d];
        const float4* pr = (const float4*)(Pg + d * DHEAD);
        #pragma unroll
        for (int i = 0; i < DHEAD / 4; i++) {
            float4 p = __ldg(&pr[i]);
            out[4 * i + 0] = fmaf(qd, p.x, out[4 * i + 0]);
            out[4 * i + 1] = fmaf(qd, p.y, out[4 * i + 1]);
            out[4 * i + 2] = fmaf(qd, p.z, out[4 * i + 2]);
            out[4 * i + 3] = fmaf(qd, p.w, out[4 * i + 3]);
        }
    }

    for (int j = 0; j <= tid; j++) {
        const float4* kr = (const float4*)(Ks + j * DHEAD);
        float s0 = 0.f, s1 = 0.f, s2 = 0.f, s3 = 0.f;
        #pragma unroll
        for (int i = 0; i < DHEAD / 4; i += 4) {
            float4 k0 = kr[i], k1 = kr[i + 1], k2 = kr[i + 2], k3 = kr[i + 3];
            s0 = fmaf(q[4 * i + 0], k0.x, s0); s0 = fmaf(q[4 * i + 1], k0.y, s0);
            s0 = fmaf(q[4 * i + 2], k0.z, s0); s0 = fmaf(q[4 * i + 3], k0.w, s0);
            s1 = fmaf(q[4 * i + 4], k1.x, s1); s1 = fmaf(q[4 * i + 5], k1.y, s1);
            s1 = fmaf(q[4 * i + 6], k1.z, s1); s1 = fmaf(q[4 * i + 7], k1.w, s1);
            s2 = fmaf(q[4 * i + 8], k2.x, s2); s2 = fmaf(q[4 * i + 9], k2.y, s2);
            s2 = fmaf(q[4 * i + 10], k2.z, s2); s2 = fmaf(q[4 * i + 11], k2.w, s2);
            s3 = fmaf(q[4 * i + 12], k3.x, s3); s3 = fmaf(q[4 * i + 13], k3.y, s3);
            s3 = fmaf(q[4 * i + 14], k3.z, s3); s3 = fmaf(q[4 * i + 15], k3.w, s3);
        }
        float s = (s0 + s1) + (s2 + s3);
        den += s;
        const float4* vr = (const float4*)(Vs + j * DHEAD);
        #pragma unroll
        for (int i = 0; i < DHEAD / 4; i++) {
            float4 vv4 = vr[i];
            out[4 * i + 0] = fmaf(s, vv4.x, out[4 * i + 0]);
            out[4 * i + 1] = fmaf(s, vv4.y, out[4 * i + 1]);
            out[4 * i + 2] = fmaf(s, vv4.z, out[4 * i + 2]);
            out[4 * i + 3] = fmaf(s, vv4.w, out[4 * i + 3]);
        }
    }

    float inv = 1.f / (den + DEN_EPS);
    int l = c * CSIZE + tid;
    __half* op = g_at + (size_t)l * DMODEL + h * DHEAD;
    #pragma unroll
    for (int e = 0; e < DHEAD; e += 2) {
        __half2 hv = __floats2half2_rn(out[e] * inv, out[e + 1] * inv);
        *(__half2*)&op[e] = hv;
    }
}

// ---------------- host launcher ----------------
extern "C" void kernel_launch(void* const* d_in, const int* in_sizes, int n_in,
                              void* d_out, int out_size) {
    const float* x      = (const float*)d_in[0];
    const float* W_qkv  = (const float*)d_in[1];
    const float* b_qkv  = (const float*)d_in[2];
    const float* W_sem  = (const float*)d_in[3];
    const float* b_sem  = (const float*)d_in[4];
    const float* W_ctx  = (const float*)d_in[5];
    const float* b_ctx  = (const float*)d_in[6];
    const float* W_proj = (const float*)d_in[7];
    const float* b_proj = (const float*)d_in[8];
    const float* ln_g   = (const float*)d_in[9];
    const float* ln_b   = (const float*)d_in[10];
    float* out = (float*)d_out;

    __half *p_a, *p_x, *p_wq, *p_ws, *p_wp, *p_at;
    float *p_bsc, *p_qkv, *p_semctx;
    cudaGetSymbolAddress((void**)&p_a, g_a);
    cudaGetSymbolAddress((void**)&p_x, g_x);
    cudaGetSymbolAddress((void**)&p_wq, g_wqkv);
    cudaGetSymbolAddress((void**)&p_ws, g_wsc);
    cudaGetSymbolAddress((void**)&p_wp, g_wpr);
    cudaGetSymbolAddress((void**)&p_at, g_at);
    cudaGetSymbolAddress((void**)&p_bsc, g_bsc);
    cudaGetSymbolAddress((void**)&p_qkv, g_qkv);
    cudaGetSymbolAddress((void**)&p_semctx, g_semctx);

    cudaFuncSetAttribute(gemm_mma, cudaFuncAttributeMaxDynamicSharedMemorySize, GEMM_SMEM);
    cudaFuncSetAttribute(feat_sums_kernel, cudaFuncAttributeMaxDynamicSharedMemorySize, SMEM_FS);
    cudaFuncSetAttribute(chunk_attn_kernel, cudaFuncAttributeMaxDynamicSharedMemorySize, SMEM_C);

    // weight prep (single launch) + biases + LN
    transpose_split_all<<<dim3(192, 24), dim3(32, 8)>>>(W_qkv, W_sem, W_ctx, W_proj);
    concat_bias<<<12, 256>>>(b_sem, b_ctx);
    ln_split_kernel<<<LSEQ, 256>>>(x, ln_g, ln_b);

    // fp16 tensor-core GEMMs
    gemm_mma<<<dim3(2304 / 128, LSEQ / 128), 256, GEMM_SMEM>>>(p_a, p_wq, b_qkv, p_qkv, 2304);
    gemm_mma<<<dim3(3072 / 128, LSEQ / 128), 256, GEMM_SMEM>>>(p_x, p_ws, p_bsc, p_semctx, 3072);

    // fused gate/features + chunk state sums
    feat_sums_kernel<<<NHEAD * NCHUNK, 256, SMEM_FS>>>();

    // scan + causal output
    scan_states_kernel<<<dim3(NHEAD, 4), 256>>>();
    chunk_attn_kernel<<<NHEAD * NCHUNK, 128, SMEM_C>>>();

    // output projection
    gemm_mma<<<dim3(768 / 128, LSEQ / 128), 256, GEMM_SMEM>>>(p_at, p_wp, b_proj, out, 768);
}